// round 14
// baseline (speedup 1.0000x reference)
#include <cuda_runtime.h>

// Problem constants (fixed by the reference)
#define T_TOTAL   262144
#define S_DIM     512
#define K_ROWS    258       // NUM_KNOTS + DEGREE - 1
#define NKNOTS    262       // NUM_KNOTS + 2*DEGREE
#define DEG       3

// Scratch (allocation-free per harness rules)
__device__ float  g_rowsum[K_ROWS];
__device__ float4 g_coef[T_TOTAL];   // 4 MB  (L2-resident between kernels)
__device__ int    g_base[T_TOTAL];   // 1 MB

// ---------------------------------------------------------------------------
// Kernel 1: rowsum[r] = sum_s W[r, s]   (258 x 512, negligible cost)
// ---------------------------------------------------------------------------
__global__ void rowsum_kernel(const float* __restrict__ weights) {
    const int row = blockIdx.x;
    float s = 0.0f;
    for (int c = threadIdx.x; c < S_DIM; c += blockDim.x)
        s += weights[row * S_DIM + c];
    #pragma unroll
    for (int o = 16; o > 0; o >>= 1)
        s += __shfl_down_sync(0xffffffffu, s, o);
    __shared__ float ws[4];
    const int w = threadIdx.x >> 5;
    if ((threadIdx.x & 31) == 0) ws[w] = s;
    __syncthreads();
    if (threadIdx.x == 0)
        g_rowsum[row] = ws[0] + ws[1] + ws[2] + ws[3];
}

// ---------------------------------------------------------------------------
// Kernel 2: one thread per time — span search + de Boor.
// Writes coeffs (float4) + base to device globals; per-time sum to out tail.
// ---------------------------------------------------------------------------
__global__ __launch_bounds__(512)
void coeff_kernel(const float* __restrict__ times,
                  const float* __restrict__ knots,
                  float* __restrict__ out)
{
    __shared__ float s_knots[NKNOTS];
    const int tid  = threadIdx.x;
    const int tIdx = blockIdx.x * 512 + tid;

    if (tid < NKNOTS) s_knots[tid] = knots[tid];
    __syncthreads();

    const float t = times[tIdx];
    float c0 = 0.f, c1 = 0.f, c2 = 0.f, c3 = 0.f, sum = 0.f;
    int base = 0;

    // Valid half-open span exists only if t < knots[258] (= t_max).
    // t == t_max => reference basis row is all zeros.
    if (t < s_knots[NKNOTS - DEG - 1]) {
        // binary search: largest i in [3, 257] with knots[i] <= t
        int lo = DEG, hi = NKNOTS - DEG - 2;   // 3 .. 257
        while (lo < hi) {
            const int mid = (lo + hi + 1) >> 1;
            if (s_knots[mid] <= t) lo = mid; else hi = mid - 1;
        }
        const int i = lo;  // knots[i] <= t < knots[i+1], non-empty span

        // Local de Boor triangle (all denominators > 0 in a valid span;
        // algebraically identical to the reference's recursion).
        float Nv[DEG + 1], left[DEG + 1], right[DEG + 1];
        Nv[0] = 1.0f;
        #pragma unroll
        for (int j = 1; j <= DEG; j++) {
            left[j]  = t - s_knots[i + 1 - j];
            right[j] = s_knots[i + j] - t;
            float saved = 0.0f;
            #pragma unroll
            for (int r = 0; r < j; r++) {
                const float temp = Nv[r] / (right[r + 1] + left[j - r]);
                Nv[r] = saved + right[r + 1] * temp;
                saved = left[j - r] * temp;
            }
            Nv[j] = saved;
        }
        base = i - DEG;
        c0 = Nv[0]; c1 = Nv[1]; c2 = Nv[2]; c3 = Nv[3];
        sum = c0 * g_rowsum[base]     + c1 * g_rowsum[base + 1]
            + c2 * g_rowsum[base + 2] + c3 * g_rowsum[base + 3];
    }

    g_coef[tIdx] = make_float4(c0, c1, c2, c3);
    g_base[tIdx] = base;
    // b_splines_sum lives after the T*S b_splines block
    out[(size_t)T_TOTAL * S_DIM + tIdx] = sum;
}

// ---------------------------------------------------------------------------
// Kernel 3: persistent, barrier-free streaming combine.
// Grid = exact resident capacity (set by host). Each block owns a contiguous
// balanced range of 4-time tiles (contiguity keeps the span base ~constant so
// the register weight-cache reloads only ~2x per block). Max imbalance is
// one tile (~0.7%) instead of the ~8% wave-quantization tail.
// ---------------------------------------------------------------------------
__global__ __launch_bounds__(512)
void stream_kernel(const float* __restrict__ weights,
                   float* __restrict__ out)
{
    const int tl   = threadIdx.x >> 7;    // 0..3: time sub-slot (warp-uniform)
    const int lane = threadIdx.x & 127;   // column group
    const int col  = lane << 2;           // 4 columns per thread

    const int total_tiles = T_TOTAL / 4;  // 65536, each tile = 4 times
    const int nb = gridDim.x;
    const int b  = blockIdx.x;
    const int q  = total_tiles / nb;
    const int r  = total_tiles % nb;
    const int start = b * q + (b < r ? b : r);
    const int cnt   = q + (b < r ? 1 : 0);

    int t = (start << 2) + tl;

    // Prime the weight-row register cache
    int curBase = g_base[t];
    const float* wp = weights + (size_t)curBase * S_DIM + col;
    float4 w0 = __ldg((const float4*)(wp));
    float4 w1 = __ldg((const float4*)(wp + S_DIM));
    float4 w2 = __ldg((const float4*)(wp + 2 * S_DIM));
    float4 w3 = __ldg((const float4*)(wp + 3 * S_DIM));

    float* out_ptr = out + (size_t)t * S_DIM + col;

    #pragma unroll 2
    for (int it = 0; it < cnt; ++it) {
        const int base = g_base[t];        // broadcast load, L1/L2 hit
        if (base != curBase) {             // warp-uniform, rare
            curBase = base;
            const float* wq = weights + (size_t)base * S_DIM + col;
            w0 = __ldg((const float4*)(wq));
            w1 = __ldg((const float4*)(wq + S_DIM));
            w2 = __ldg((const float4*)(wq + 2 * S_DIM));
            w3 = __ldg((const float4*)(wq + 3 * S_DIM));
        }
        const float4 c = g_coef[t];        // LDG.128 broadcast, L2 hit

        float4 o;
        o.x = c.x * w0.x + c.y * w1.x + c.z * w2.x + c.w * w3.x;
        o.y = c.x * w0.y + c.y * w1.y + c.z * w2.y + c.w * w3.y;
        o.z = c.x * w0.z + c.y * w1.z + c.z * w2.z + c.w * w3.z;
        o.w = c.x * w0.w + c.y * w1.w + c.z * w2.w + c.w * w3.w;

        // Streaming store: 512 MB with zero reuse — don't pollute L2.
        __stcs((float4*)out_ptr, o);

        t       += 4;
        out_ptr += 4 * S_DIM;
    }
}

// ---------------------------------------------------------------------------
// Launch: inputs are (times, weights, knots) per metadata order.
// Output buffer: [ b_splines (T*S floats) | b_splines_sum (T floats) ].
// ---------------------------------------------------------------------------
extern "C" void kernel_launch(void* const* d_in, const int* in_sizes, int n_in,
                              void* d_out, int out_size) {
    const float* times   = (const float*)d_in[0];
    const float* weights = (const float*)d_in[1];
    const float* knots   = (const float*)d_in[2];
    float* out = (float*)d_out;

    // Size the persistent grid to exactly the resident capacity (<= C is
    // mandatory: oversubscribing a persistent grid doubles the runtime).
    static int grid_b = 0;
    if (grid_b == 0) {
        int dev = 0, nsm = 0, occ = 0;
        cudaGetDevice(&dev);
        cudaDeviceGetAttribute(&nsm, cudaDevAttrMultiProcessorCount, dev);
        cudaOccupancyMaxActiveBlocksPerMultiprocessor(&occ, stream_kernel, 512, 0);
        if (occ < 1) occ = 1;
        grid_b = nsm * occ;
        if (grid_b < 1) grid_b = 444;
        if (grid_b > T_TOTAL / 4) grid_b = T_TOTAL / 4;
    }

    rowsum_kernel<<<K_ROWS, 128>>>(weights);
    coeff_kernel<<<T_TOTAL / 512, 512>>>(times, knots, out);
    stream_kernel<<<grid_b, 512>>>(weights, out);
}

// round 15
// speedup vs baseline: 1.1673x; 1.1673x over previous
#include <cuda_runtime.h>

// Problem constants (fixed by the reference)
#define T_TOTAL   262144
#define S_DIM     512
#define K_ROWS    258       // NUM_KNOTS + DEGREE - 1
#define NKNOTS    262       // NUM_KNOTS + 2*DEGREE
#define DEG       3

#define TIMES_PER_BLOCK 64
#define NBLOCKS (T_TOTAL / TIMES_PER_BLOCK)   // 4096

// Scratch for weight row sums (allocation-free per harness rules)
__device__ float g_rowsum[K_ROWS];

// ---------------------------------------------------------------------------
// Kernel 1: rowsum[r] = sum_s W[r, s]. 258 blocks x 128 threads,
// one float4 per thread (single LDG.128) -> warp reduce -> smem reduce.
// ---------------------------------------------------------------------------
__global__ void rowsum_kernel(const float* __restrict__ weights) {
    const int row = blockIdx.x;
    const float4 v = __ldg((const float4*)(weights + row * S_DIM) + threadIdx.x);
    float s = v.x + v.y + v.z + v.w;
    #pragma unroll
    for (int o = 16; o > 0; o >>= 1)
        s += __shfl_down_sync(0xffffffffu, s, o);
    __shared__ float ws[4];
    if ((threadIdx.x & 31) == 0) ws[threadIdx.x >> 5] = s;
    __syncthreads();
    if (threadIdx.x == 0)
        g_rowsum[row] = ws[0] + ws[1] + ws[2] + ws[3];
}

// ---------------------------------------------------------------------------
// Kernel 2: 512 threads/block, 64 times/block (R8 structure).
//   Phase A: stage knots in smem.
//   Phase B: threads 0..63 do independent span search + de Boor, write
//            coeffs (float4) + base to smem, per-time sum to gmem.
//   Phase C: streaming combine + store. Weight rows register-cached.
//            Sorted times => s_base monotone => s_base[0]==s_base[63]
//            means the whole block shares one span (~94% of blocks):
//            take a branch-free fully-batched fast path.
// NOTE: natural register allocation — forcing 32 regs spills the weight
// cache (R10 regression); splitting kernels adds traffic (R14 regression).
// ---------------------------------------------------------------------------
__global__ __launch_bounds__(512)
void bspline_kernel(const float* __restrict__ times,
                    const float* __restrict__ weights,
                    const float* __restrict__ knots,
                    float* __restrict__ out)
{
    __shared__ float  s_knots[NKNOTS];
    __shared__ float4 s_c[TIMES_PER_BLOCK];
    __shared__ int    s_base[TIMES_PER_BLOCK];

    const int tid = threadIdx.x;
    const int t0  = blockIdx.x * TIMES_PER_BLOCK;

    // Phase A: knots -> smem
    if (tid < NKNOTS) s_knots[tid] = knots[tid];
    __syncthreads();

    // Phase B: 64 parallel coefficient computations
    if (tid < TIMES_PER_BLOCK) {
        const float t = times[t0 + tid];
        float c0 = 0.f, c1 = 0.f, c2 = 0.f, c3 = 0.f, sum = 0.f;
        int base = 0;

        // Valid half-open span exists only if t < knots[258] (= t_max).
        // t == t_max => reference basis row is all zeros.
        if (t < s_knots[NKNOTS - DEG - 1]) {
            // binary search: largest i in [3, 257] with knots[i] <= t
            int lo = DEG, hi = NKNOTS - DEG - 2;   // 3 .. 257
            while (lo < hi) {
                const int mid = (lo + hi + 1) >> 1;
                if (s_knots[mid] <= t) lo = mid; else hi = mid - 1;
            }
            const int i = lo;  // knots[i] <= t < knots[i+1], non-empty span

            // Local de Boor triangle (all denominators > 0 in a valid span;
            // algebraically identical to the reference's recursion).
            float Nv[DEG + 1], left[DEG + 1], right[DEG + 1];
            Nv[0] = 1.0f;
            #pragma unroll
            for (int j = 1; j <= DEG; j++) {
                left[j]  = t - s_knots[i + 1 - j];
                right[j] = s_knots[i + j] - t;
                float saved = 0.0f;
                #pragma unroll
                for (int r = 0; r < j; r++) {
                    const float temp = Nv[r] / (right[r + 1] + left[j - r]);
                    Nv[r] = saved + right[r + 1] * temp;
                    saved = left[j - r] * temp;
                }
                Nv[j] = saved;
            }
            base = i - DEG;
            c0 = Nv[0]; c1 = Nv[1]; c2 = Nv[2]; c3 = Nv[3];
            sum = c0 * g_rowsum[base]     + c1 * g_rowsum[base + 1]
                + c2 * g_rowsum[base + 2] + c3 * g_rowsum[base + 3];
        }

        s_c[tid]    = make_float4(c0, c1, c2, c3);
        s_base[tid] = base;
        // b_splines_sum lives after the T*S b_splines block
        out[(size_t)T_TOTAL * S_DIM + (t0 + tid)] = sum;
    }
    __syncthreads();

    // Phase C: streaming combine + store with register-cached weight rows
    const int tl   = tid >> 7;    // 0..3: time sub-slot (warp-uniform)
    const int lane = tid & 127;   // column group
    const int col  = lane << 2;   // 4 columns per thread

    int curBase = s_base[tl];
    const float* wp = weights + (size_t)curBase * S_DIM + col;
    float4 w0 = __ldg((const float4*)(wp));
    float4 w1 = __ldg((const float4*)(wp + S_DIM));
    float4 w2 = __ldg((const float4*)(wp + 2 * S_DIM));
    float4 w3 = __ldg((const float4*)(wp + 3 * S_DIM));

    float* out_ptr = out + (size_t)(t0 + tl) * S_DIM + col;

    if (s_base[0] == s_base[TIMES_PER_BLOCK - 1]) {
        // Fast path (~94% of blocks): single span for the whole block.
        // Branch-free: pure LDS -> FMA -> STG stream, deep store batching.
        #pragma unroll 4
        for (int it = 0; it < TIMES_PER_BLOCK / 4; ++it) {
            const float4 c = s_c[(it << 2) + tl];
            float4 o;
            o.x = c.x * w0.x + c.y * w1.x + c.z * w2.x + c.w * w3.x;
            o.y = c.x * w0.y + c.y * w1.y + c.z * w2.y + c.w * w3.y;
            o.z = c.x * w0.z + c.y * w1.z + c.z * w2.z + c.w * w3.z;
            o.w = c.x * w0.w + c.y * w1.w + c.z * w2.w + c.w * w3.w;
            __stcs((float4*)out_ptr, o);   // streaming: no L2 pollution
            out_ptr += 4 * S_DIM;
        }
    } else {
        // Slow path: span changes inside the block (checked per iteration,
        // warp-uniform branch, reload is rare).
        #pragma unroll 2
        for (int it = 0; it < TIMES_PER_BLOCK / 4; ++it) {
            const int slot = (it << 2) + tl;
            const int base = s_base[slot];
            if (base != curBase) {
                curBase = base;
                const float* wq = weights + (size_t)base * S_DIM + col;
                w0 = __ldg((const float4*)(wq));
                w1 = __ldg((const float4*)(wq + S_DIM));
                w2 = __ldg((const float4*)(wq + 2 * S_DIM));
                w3 = __ldg((const float4*)(wq + 3 * S_DIM));
            }
            const float4 c = s_c[slot];
            float4 o;
            o.x = c.x * w0.x + c.y * w1.x + c.z * w2.x + c.w * w3.x;
            o.y = c.x * w0.y + c.y * w1.y + c.z * w2.y + c.w * w3.y;
            o.z = c.x * w0.z + c.y * w1.z + c.z * w2.z + c.w * w3.z;
            o.w = c.x * w0.w + c.y * w1.w + c.z * w2.w + c.w * w3.w;
            __stcs((float4*)out_ptr, o);
            out_ptr += 4 * S_DIM;
        }
    }
}

// ---------------------------------------------------------------------------
// Launch: inputs are (times, weights, knots) per metadata order.
// Output buffer: [ b_splines (T*S floats) | b_splines_sum (T floats) ].
// ---------------------------------------------------------------------------
extern "C" void kernel_launch(void* const* d_in, const int* in_sizes, int n_in,
                              void* d_out, int out_size) {
    const float* times   = (const float*)d_in[0];
    const float* weights = (const float*)d_in[1];
    const float* knots   = (const float*)d_in[2];
    float* out = (float*)d_out;

    rowsum_kernel<<<K_ROWS, 128>>>(weights);
    bspline_kernel<<<NBLOCKS, 512>>>(times, weights, knots, out);
}

// round 16
// speedup vs baseline: 1.1716x; 1.0036x over previous
#include <cuda_runtime.h>

// Problem constants (fixed by the reference)
#define T_TOTAL   262144
#define S_DIM     512
#define K_ROWS    258       // NUM_KNOTS + DEGREE - 1
#define NKNOTS    262       // NUM_KNOTS + 2*DEGREE
#define DEG       3

#define TIMES_PER_BLOCK 64
#define NBLOCKS (T_TOTAL / TIMES_PER_BLOCK)   // 4096

// Scratch for weight row sums (allocation-free per harness rules)
__device__ float g_rowsum[K_ROWS];

// ---------------------------------------------------------------------------
// Kernel 1: rowsum[r] = sum_s W[r, s]. 258 blocks x 128 threads,
// one float4 per thread (single LDG.128) -> warp reduce -> smem reduce.
// ---------------------------------------------------------------------------
__global__ void rowsum_kernel(const float* __restrict__ weights) {
    const int row = blockIdx.x;
    const float4 v = __ldg((const float4*)(weights + row * S_DIM) + threadIdx.x);
    float s = v.x + v.y + v.z + v.w;
    #pragma unroll
    for (int o = 16; o > 0; o >>= 1)
        s += __shfl_down_sync(0xffffffffu, s, o);
    __shared__ float ws[4];
    if ((threadIdx.x & 31) == 0) ws[threadIdx.x >> 5] = s;
    __syncthreads();
    if (threadIdx.x == 0)
        g_rowsum[row] = ws[0] + ws[1] + ws[2] + ws[3];
}

// ---------------------------------------------------------------------------
// Kernel 2: 512 threads/block, 64 times/block (R8 structure).
//   Phase A: stage knots in smem.
//   Phase B: threads 0..63 do independent span search + de Boor, write
//            coeffs (float4) + base to smem, per-time sum to gmem.
//   Phase C: streaming combine + store. Weight rows register-cached.
//            Sorted times => s_base monotone => s_base[0]==s_base[63]
//            means the whole block shares one span (~94% of blocks):
//            take a branch-free fully-batched fast path.
// NOTE: natural register allocation — forcing 32 regs spills the weight
// cache (R10 regression); splitting kernels adds traffic (R14 regression).
// ---------------------------------------------------------------------------
__global__ __launch_bounds__(512)
void bspline_kernel(const float* __restrict__ times,
                    const float* __restrict__ weights,
                    const float* __restrict__ knots,
                    float* __restrict__ out)
{
    __shared__ float  s_knots[NKNOTS];
    __shared__ float4 s_c[TIMES_PER_BLOCK];
    __shared__ int    s_base[TIMES_PER_BLOCK];

    const int tid = threadIdx.x;
    const int t0  = blockIdx.x * TIMES_PER_BLOCK;

    // Phase A: knots -> smem
    if (tid < NKNOTS) s_knots[tid] = knots[tid];
    __syncthreads();

    // Phase B: 64 parallel coefficient computations
    if (tid < TIMES_PER_BLOCK) {
        const float t = times[t0 + tid];
        float c0 = 0.f, c1 = 0.f, c2 = 0.f, c3 = 0.f, sum = 0.f;
        int base = 0;

        // Valid half-open span exists only if t < knots[258] (= t_max).
        // t == t_max => reference basis row is all zeros.
        if (t < s_knots[NKNOTS - DEG - 1]) {
            // binary search: largest i in [3, 257] with knots[i] <= t
            int lo = DEG, hi = NKNOTS - DEG - 2;   // 3 .. 257
            while (lo < hi) {
                const int mid = (lo + hi + 1) >> 1;
                if (s_knots[mid] <= t) lo = mid; else hi = mid - 1;
            }
            const int i = lo;  // knots[i] <= t < knots[i+1], non-empty span

            // Local de Boor triangle (all denominators > 0 in a valid span;
            // algebraically identical to the reference's recursion).
            float Nv[DEG + 1], left[DEG + 1], right[DEG + 1];
            Nv[0] = 1.0f;
            #pragma unroll
            for (int j = 1; j <= DEG; j++) {
                left[j]  = t - s_knots[i + 1 - j];
                right[j] = s_knots[i + j] - t;
                float saved = 0.0f;
                #pragma unroll
                for (int r = 0; r < j; r++) {
                    const float temp = Nv[r] / (right[r + 1] + left[j - r]);
                    Nv[r] = saved + right[r + 1] * temp;
                    saved = left[j - r] * temp;
                }
                Nv[j] = saved;
            }
            base = i - DEG;
            c0 = Nv[0]; c1 = Nv[1]; c2 = Nv[2]; c3 = Nv[3];
            sum = c0 * g_rowsum[base]     + c1 * g_rowsum[base + 1]
                + c2 * g_rowsum[base + 2] + c3 * g_rowsum[base + 3];
        }

        s_c[tid]    = make_float4(c0, c1, c2, c3);
        s_base[tid] = base;
        // b_splines_sum lives after the T*S b_splines block
        out[(size_t)T_TOTAL * S_DIM + (t0 + tid)] = sum;
    }
    __syncthreads();

    // Phase C: streaming combine + store with register-cached weight rows
    const int tl   = tid >> 7;    // 0..3: time sub-slot (warp-uniform)
    const int lane = tid & 127;   // column group
    const int col  = lane << 2;   // 4 columns per thread

    int curBase = s_base[tl];
    const float* wp = weights + (size_t)curBase * S_DIM + col;
    float4 w0 = __ldg((const float4*)(wp));
    float4 w1 = __ldg((const float4*)(wp + S_DIM));
    float4 w2 = __ldg((const float4*)(wp + 2 * S_DIM));
    float4 w3 = __ldg((const float4*)(wp + 3 * S_DIM));

    float* out_ptr = out + (size_t)(t0 + tl) * S_DIM + col;

    if (s_base[0] == s_base[TIMES_PER_BLOCK - 1]) {
        // Fast path (~94% of blocks): single span for the whole block.
        // Branch-free: pure LDS -> FMA -> STG stream, deep store batching.
        #pragma unroll 4
        for (int it = 0; it < TIMES_PER_BLOCK / 4; ++it) {
            const float4 c = s_c[(it << 2) + tl];
            float4 o;
            o.x = c.x * w0.x + c.y * w1.x + c.z * w2.x + c.w * w3.x;
            o.y = c.x * w0.y + c.y * w1.y + c.z * w2.y + c.w * w3.y;
            o.z = c.x * w0.z + c.y * w1.z + c.z * w2.z + c.w * w3.z;
            o.w = c.x * w0.w + c.y * w1.w + c.z * w2.w + c.w * w3.w;
            __stcs((float4*)out_ptr, o);   // streaming: no L2 pollution
            out_ptr += 4 * S_DIM;
        }
    } else {
        // Slow path: span changes inside the block (checked per iteration,
        // warp-uniform branch, reload is rare).
        #pragma unroll 2
        for (int it = 0; it < TIMES_PER_BLOCK / 4; ++it) {
            const int slot = (it << 2) + tl;
            const int base = s_base[slot];
            if (base != curBase) {
                curBase = base;
                const float* wq = weights + (size_t)base * S_DIM + col;
                w0 = __ldg((const float4*)(wq));
                w1 = __ldg((const float4*)(wq + S_DIM));
                w2 = __ldg((const float4*)(wq + 2 * S_DIM));
                w3 = __ldg((const float4*)(wq + 3 * S_DIM));
            }
            const float4 c = s_c[slot];
            float4 o;
            o.x = c.x * w0.x + c.y * w1.x + c.z * w2.x + c.w * w3.x;
            o.y = c.x * w0.y + c.y * w1.y + c.z * w2.y + c.w * w3.y;
            o.z = c.x * w0.z + c.y * w1.z + c.z * w2.z + c.w * w3.z;
            o.w = c.x * w0.w + c.y * w1.w + c.z * w2.w + c.w * w3.w;
            __stcs((float4*)out_ptr, o);
            out_ptr += 4 * S_DIM;
        }
    }
}

// ---------------------------------------------------------------------------
// Launch: inputs are (times, weights, knots) per metadata order.
// Output buffer: [ b_splines (T*S floats) | b_splines_sum (T floats) ].
// ---------------------------------------------------------------------------
extern "C" void kernel_launch(void* const* d_in, const int* in_sizes, int n_in,
                              void* d_out, int out_size) {
    const float* times   = (const float*)d_in[0];
    const float* weights = (const float*)d_in[1];
    const float* knots   = (const float*)d_in[2];
    float* out = (float*)d_out;

    rowsum_kernel<<<K_ROWS, 128>>>(weights);
    bspline_kernel<<<NBLOCKS, 512>>>(times, weights, knots, out);
}